// round 2
// baseline (speedup 1.0000x reference)
#include <cuda_runtime.h>
#include <math.h>

#define BB 128
#define TT 256
#define IN 512
#define HH 1024
#define OUT 512
#define NG 4096  // 4*HH, gate-interleaved: n = j*4 + g, g in {f,i,c,o}

// ---------------- static device scratch ----------------
__device__ float g_A[(size_t)TT * BB * NG];   // [t][b][n]  x-contribution + bias (512 MB)
__device__ float g_hs[(size_t)BB * TT * HH];  // [b][t][j]  (128 MB)
__device__ float g_h[2][BB * HH];             // ping-pong hidden state
__device__ float g_c[BB * HH];                // cell state
__device__ float g_WxT[(size_t)IN * NG];      // [k][n]
__device__ float g_WhT[(size_t)HH * NG];      // [k][n]
__device__ float g_WoT[(size_t)HH * OUT];     // [k][o]
__device__ float g_bias[NG];

__device__ __forceinline__ float fast_sigmoid(float v) {
    return 1.0f / (1.0f + __expf(-v));
}
__device__ __forceinline__ float fast_tanh(float v) {
    // tanh(v) = 2*sigmoid(2v) - 1
    float e = __expf(-2.0f * v);
    return (1.0f - e) / (1.0f + e);
}

// ---------------- packing / init ----------------
__global__ void pack_weights_kernel(const float* __restrict__ Wf, const float* __restrict__ Wi,
                                    const float* __restrict__ Wc, const float* __restrict__ Wo) {
    int idx = blockIdx.x * blockDim.x + threadIdx.x;
    const int total = (IN + HH) * NG;
    if (idx >= total) return;
    int k = idx / NG;
    int n = idx % NG;
    int g = n & 3, j = n >> 2;
    const float* W = (g == 0) ? Wf : (g == 1) ? Wi : (g == 2) ? Wc : Wo;
    float v = __ldg(W + (size_t)j * (IN + HH) + k);
    if (k < IN)
        g_WxT[(size_t)k * NG + n] = v;
    else
        g_WhT[(size_t)(k - IN) * NG + n] = v;
}

__global__ void pack_misc_kernel(const float* __restrict__ bf, const float* __restrict__ bi,
                                 const float* __restrict__ bc, const float* __restrict__ bo,
                                 const float* __restrict__ Wout) {
    int idx = blockIdx.x * blockDim.x + threadIdx.x;
    if (idx < NG) {
        int g = idx & 3, j = idx >> 2;
        const float* bsrc = (g == 0) ? bf : (g == 1) ? bi : (g == 2) ? bc : bo;
        g_bias[idx] = __ldg(bsrc + j);
    }
    if (idx < HH * OUT) {
        int k = idx / OUT, o = idx % OUT;
        g_WoT[idx] = __ldg(Wout + (size_t)o * HH + k);
    }
    if (idx < BB * HH) {
        g_h[0][idx] = 0.0f;
        g_c[idx] = 0.0f;
    }
}

// ---------------- GEMM 1: A[t][b][n] = x @ WxT + bias ----------------
// M = BB*TT (m = b*TT + t), K = IN, N = NG.  BM=128 BN=64 BK=16, 256 thr, 8x4/thr.
__global__ void __launch_bounds__(256) gemm_x_kernel(const float* __restrict__ x) {
    __shared__ float As[16][132];
    __shared__ float Bs[16][64];
    int tid = threadIdx.x;
    int m0 = blockIdx.y * 128;
    int n0 = blockIdx.x * 64;
    int tx = tid % 16, ty = tid / 16;

    float acc[8][4] = {};

    int la_row = tid >> 2;            // 0..63
    int la_k = (tid & 3) * 4;         // 0,4,8,12
    int lb_n = (tid & 15) * 4;        // 0..60
    int lb_k = tid >> 4;              // 0..15

    for (int k0 = 0; k0 < IN; k0 += 16) {
#pragma unroll
        for (int p = 0; p < 2; p++) {
            int row = la_row + p * 64;
            float4 v = __ldg((const float4*)(x + (size_t)(m0 + row) * IN + k0 + la_k));
            As[la_k + 0][row] = v.x;
            As[la_k + 1][row] = v.y;
            As[la_k + 2][row] = v.z;
            As[la_k + 3][row] = v.w;
        }
        float4 w = *(const float4*)(g_WxT + (size_t)(k0 + lb_k) * NG + n0 + lb_n);
        *(float4*)&Bs[lb_k][lb_n] = w;
        __syncthreads();
#pragma unroll
        for (int kk = 0; kk < 16; kk++) {
            float a[8], bv[4];
            float4 a0 = *(const float4*)&As[kk][ty * 8];
            float4 a1 = *(const float4*)&As[kk][ty * 8 + 4];
            a[0] = a0.x; a[1] = a0.y; a[2] = a0.z; a[3] = a0.w;
            a[4] = a1.x; a[5] = a1.y; a[6] = a1.z; a[7] = a1.w;
            float4 b0 = *(const float4*)&Bs[kk][tx * 4];
            bv[0] = b0.x; bv[1] = b0.y; bv[2] = b0.z; bv[3] = b0.w;
#pragma unroll
            for (int i = 0; i < 8; i++)
#pragma unroll
                for (int j = 0; j < 4; j++) acc[i][j] += a[i] * bv[j];
        }
        __syncthreads();
    }
#pragma unroll
    for (int i = 0; i < 8; i++) {
        int m = m0 + ty * 8 + i;
        int b = m / TT, t = m % TT;
        size_t base = (size_t)t * BB * NG + (size_t)b * NG + n0 + tx * 4;
#pragma unroll
        for (int j = 0; j < 4; j++) g_A[base + j] = acc[i][j] + g_bias[n0 + tx * 4 + j];
    }
}

// ---------------- LSTM step: P = h @ WhT, fuse gates + c/h update ----------------
// M = BB = 128 (whole batch in one block-row), N = NG, BN=32 (8 units), BK=16.
// 256 threads, each thread: TM=4 batches x TN=4 (all 4 gates of one unit j).
__global__ void __launch_bounds__(256) lstm_step_kernel(int t, int par) {
    __shared__ float Hs[16][132];
    __shared__ float Ws[16][32];
    int tid = threadIdx.x;
    int n0 = blockIdx.x * 32;
    int tx = tid % 8, ty = tid / 8;   // tx: unit in block (0..7), ty: batch group (0..31)

    const float* hin = g_h[par];
    float* hout = g_h[par ^ 1];

    float acc[4][4] = {};

    int la_b = tid >> 2;              // 0..63
    int la_k = (tid & 3) * 4;
    int lb_n = (tid & 15) * 2;        // 0..30
    int lb_k = tid >> 4;              // 0..15

    for (int k0 = 0; k0 < HH; k0 += 16) {
#pragma unroll
        for (int p = 0; p < 2; p++) {
            int bb = la_b + p * 64;
            float4 v = *(const float4*)(hin + (size_t)bb * HH + k0 + la_k);
            Hs[la_k + 0][bb] = v.x;
            Hs[la_k + 1][bb] = v.y;
            Hs[la_k + 2][bb] = v.z;
            Hs[la_k + 3][bb] = v.w;
        }
        float2 w = *(const float2*)(g_WhT + (size_t)(k0 + lb_k) * NG + n0 + lb_n);
        *(float2*)&Ws[lb_k][lb_n] = w;
        __syncthreads();
#pragma unroll
        for (int kk = 0; kk < 16; kk++) {
            float4 av = *(const float4*)&Hs[kk][ty * 4];
            float a[4] = {av.x, av.y, av.z, av.w};
            float4 wv = *(const float4*)&Ws[kk][tx * 4];
            float bv[4] = {wv.x, wv.y, wv.z, wv.w};
#pragma unroll
            for (int i = 0; i < 4; i++)
#pragma unroll
                for (int j = 0; j < 4; j++) acc[i][j] += a[i] * bv[j];
        }
        __syncthreads();
    }

    // epilogue: this thread owns unit j for 4 batches, all 4 gates.
    int j = (n0 >> 2) + tx;
#pragma unroll
    for (int i = 0; i < 4; i++) {
        int bb = ty * 4 + i;
        const float4 av = *(const float4*)(g_A + (size_t)t * BB * NG + (size_t)bb * NG + n0 + tx * 4);
        float pf = acc[i][0] + av.x;
        float pi = acc[i][1] + av.y;
        float pc = acc[i][2] + av.z;
        float po = acc[i][3] + av.w;
        float fg = fast_sigmoid(pf);
        float ig = fast_sigmoid(pi);
        float ct = fast_tanh(pc);
        float og = fast_sigmoid(po);
        float c = g_c[(size_t)bb * HH + j];
        float cn = fg * c + ig * ct;
        float hn = og * fast_tanh(cn);
        g_c[(size_t)bb * HH + j] = cn;
        hout[(size_t)bb * HH + j] = hn;
        g_hs[((size_t)bb * TT + t) * HH + j] = hn;
    }
}

// ---------------- GEMM 3: out[m][o] = hs[m][:] @ WoT + b_out ----------------
// M = BB*TT (m = b*TT+t, matches hs layout), K = HH, N = OUT.
__global__ void __launch_bounds__(256) gemm_out_kernel(const float* __restrict__ bout,
                                                       float* __restrict__ out) {
    __shared__ float As[16][132];
    __shared__ float Bs[16][64];
    int tid = threadIdx.x;
    int m0 = blockIdx.y * 128;
    int n0 = blockIdx.x * 64;
    int tx = tid % 16, ty = tid / 16;

    float acc[8][4] = {};

    int la_row = tid >> 2;
    int la_k = (tid & 3) * 4;
    int lb_n = (tid & 15) * 4;
    int lb_k = tid >> 4;

    for (int k0 = 0; k0 < HH; k0 += 16) {
#pragma unroll
        for (int p = 0; p < 2; p++) {
            int row = la_row + p * 64;
            float4 v = *(const float4*)(g_hs + (size_t)(m0 + row) * HH + k0 + la_k);
            As[la_k + 0][row] = v.x;
            As[la_k + 1][row] = v.y;
            As[la_k + 2][row] = v.z;
            As[la_k + 3][row] = v.w;
        }
        float4 w = *(const float4*)(g_WoT + (size_t)(k0 + lb_k) * OUT + n0 + lb_n);
        *(float4*)&Bs[lb_k][lb_n] = w;
        __syncthreads();
#pragma unroll
        for (int kk = 0; kk < 16; kk++) {
            float a[8], bv[4];
            float4 a0 = *(const float4*)&As[kk][ty * 8];
            float4 a1 = *(const float4*)&As[kk][ty * 8 + 4];
            a[0] = a0.x; a[1] = a0.y; a[2] = a0.z; a[3] = a0.w;
            a[4] = a1.x; a[5] = a1.y; a[6] = a1.z; a[7] = a1.w;
            float4 b0 = *(const float4*)&Bs[kk][tx * 4];
            bv[0] = b0.x; bv[1] = b0.y; bv[2] = b0.z; bv[3] = b0.w;
#pragma unroll
            for (int i = 0; i < 8; i++)
#pragma unroll
                for (int j = 0; j < 4; j++) acc[i][j] += a[i] * bv[j];
        }
        __syncthreads();
    }
#pragma unroll
    for (int i = 0; i < 8; i++) {
        int m = m0 + ty * 8 + i;
        size_t base = (size_t)m * OUT + n0 + tx * 4;
#pragma unroll
        for (int j = 0; j < 4; j++) out[base + j] = acc[i][j] + __ldg(bout + n0 + tx * 4 + j);
    }
}

// ---------------- launch ----------------
extern "C" void kernel_launch(void* const* d_in, const int* in_sizes, int n_in,
                              void* d_out, int out_size) {
    const float* x    = (const float*)d_in[0];
    const float* Wf   = (const float*)d_in[1];
    const float* bf   = (const float*)d_in[2];
    const float* Wi   = (const float*)d_in[3];
    const float* bi   = (const float*)d_in[4];
    const float* Wc   = (const float*)d_in[5];
    const float* bc   = (const float*)d_in[6];
    const float* Wo   = (const float*)d_in[7];
    const float* bo   = (const float*)d_in[8];
    const float* Wout = (const float*)d_in[9];
    const float* bout = (const float*)d_in[10];
    float* out = (float*)d_out;

    {
        int total = (IN + HH) * NG;
        pack_weights_kernel<<<(total + 255) / 256, 256>>>(Wf, Wi, Wc, Wo);
    }
    {
        int total = HH * OUT;  // >= NG and >= BB*HH
        pack_misc_kernel<<<(total + 255) / 256, 256>>>(bf, bi, bc, bo, Wout);
    }

    // Parallel input GEMM: A = x @ WxT + bias
    gemm_x_kernel<<<dim3(NG / 64, (BB * TT) / 128), 256>>>(x);

    // Sequential recurrence
    for (int t = 0; t < TT; t++) {
        lstm_step_kernel<<<NG / 32, 256>>>(t, t & 1);
    }

    // Output projection
    gemm_out_kernel<<<dim3(OUT / 64, (BB * TT) / 128), 256>>>(bout, out);
}